// round 5
// baseline (speedup 1.0000x reference)
#include <cuda_runtime.h>
#include <cuda_bf16.h>
#include <stdint.h>
#include <math.h>

#define MAX_N 50000
#define MAX_E 800000
#define DHID 256
#define DIN 512
#define NB_SCAN 128

// Scratch device globals
__device__ int   g_cnt[MAX_N];
__device__ float g_dinv[MAX_N];
__device__ int   g_rowptr[MAX_N + 1];
__device__ int   g_off[MAX_N];
__device__ int   g_blocksum[NB_SCAN];
__device__ int   g_blockoff[NB_SCAN];
__device__ int   g_esrc[MAX_E];
__device__ int   g_eid[MAX_E];
__device__ float g_ecoef[MAX_E];

__device__ __nv_bfloat16 g_xh[(size_t)MAX_N * DIN];
__device__ __nv_bfloat16 g_xl[(size_t)MAX_N * DIN];
__device__ __nv_bfloat16 g_w1h[DIN * DHID];
__device__ __nv_bfloat16 g_w1l[DIN * DHID];
__device__ __nv_bfloat16 g_w2h[DHID * DHID];
__device__ __nv_bfloat16 g_w2l[DHID * DHID];
__device__ float g_h1[(size_t)MAX_N * DHID];
__device__ __nv_bfloat16 g_a1h[(size_t)MAX_N * DHID];
__device__ __nv_bfloat16 g_a1l[(size_t)MAX_N * DHID];
__device__ float g_h2[(size_t)MAX_N * DHID];
__device__ float g_agg2[(size_t)MAX_N * DHID];

// ---------------------------------------------------------------------------
// CSR build
// ---------------------------------------------------------------------------
__global__ void zero_cnt_kernel(int* cnt, int n) {
    int i = blockIdx.x * blockDim.x + threadIdx.x;
    if (i < n) cnt[i] = 0;
}

__global__ void hist_kernel(int* cnt, const int* __restrict__ dst, int e) {
    int i = blockIdx.x * blockDim.x + threadIdx.x;
    if (i < e) atomicAdd(&cnt[dst[i]], 1);
}

__global__ void dinv_kernel(const int* __restrict__ cnt, float* __restrict__ dinv, int n) {
    int i = blockIdx.x * blockDim.x + threadIdx.x;
    if (i < n) dinv[i] = rsqrtf((float)(cnt[i] + 1));
}

__global__ __launch_bounds__(256)
void scan_p1_kernel(const int* __restrict__ cnt, int* __restrict__ blocksum, int n) {
    __shared__ int red[256];
    const int chunk = (n + NB_SCAN - 1) / NB_SCAN;
    const int beg = blockIdx.x * chunk;
    const int end = min(beg + chunk, n);
    int s = 0;
    for (int i = beg + threadIdx.x; i < end; i += 256) s += cnt[i];
    red[threadIdx.x] = s;
    __syncthreads();
    for (int d = 128; d > 0; d >>= 1) {
        if (threadIdx.x < d) red[threadIdx.x] += red[threadIdx.x + d];
        __syncthreads();
    }
    if (threadIdx.x == 0) blocksum[blockIdx.x] = red[0];
}

__global__ __launch_bounds__(NB_SCAN)
void scan_p2_kernel(const int* __restrict__ blocksum, int* __restrict__ blockoff,
                    int* __restrict__ rowptr, int n) {
    __shared__ int sh[NB_SCAN];
    const int t = threadIdx.x;
    sh[t] = blocksum[t];
    __syncthreads();
    for (int d = 1; d < NB_SCAN; d <<= 1) {
        int v = (t >= d) ? sh[t - d] : 0;
        __syncthreads();
        sh[t] += v;
        __syncthreads();
    }
    blockoff[t] = (t == 0) ? 0 : sh[t - 1];
    if (t == NB_SCAN - 1) rowptr[n] = sh[NB_SCAN - 1];
}

__global__ __launch_bounds__(256)
void scan_p3_kernel(const int* __restrict__ cnt, const int* __restrict__ blockoff,
                    int* __restrict__ rowptr, int* __restrict__ off, int n) {
    __shared__ int sh[256];
    const int chunk = (n + NB_SCAN - 1) / NB_SCAN;
    const int beg = blockIdx.x * chunk;
    const int end = min(beg + chunk, n);
    int running = blockoff[blockIdx.x];
    for (int base = beg; base < end; base += 256) {
        const int i = base + threadIdx.x;
        int v = (i < end) ? cnt[i] : 0;
        sh[threadIdx.x] = v;
        __syncthreads();
        for (int d = 1; d < 256; d <<= 1) {
            int t2 = (threadIdx.x >= d) ? sh[threadIdx.x - d] : 0;
            __syncthreads();
            sh[threadIdx.x] += t2;
            __syncthreads();
        }
        if (i < end) {
            const int excl = sh[threadIdx.x] - v;
            rowptr[i] = running + excl;
            off[i] = running + excl;
        }
        running += sh[255];
        __syncthreads();
    }
}

__global__ void scatter_kernel(const int* __restrict__ src, const int* __restrict__ dst,
                               const float* __restrict__ dinv, int* __restrict__ off,
                               int* __restrict__ esrc, int* __restrict__ eid,
                               float* __restrict__ ecoef, int e) {
    int i = blockIdx.x * blockDim.x + threadIdx.x;
    if (i < e) {
        const int s = src[i];
        const int d = dst[i];
        const int pos = atomicAdd(&off[d], 1);
        esrc[pos] = s;
        eid[pos] = i;
        ecoef[pos] = dinv[s] * dinv[d];
    }
}

// ---------------------------------------------------------------------------
// fp32 -> (hi, lo) bf16 split, elementwise (for x, W1, W2)
// ---------------------------------------------------------------------------
__global__ void split_kernel(const float* __restrict__ in,
                             __nv_bfloat16* __restrict__ hi,
                             __nv_bfloat16* __restrict__ lo, int n4) {
    int i = blockIdx.x * blockDim.x + threadIdx.x;
    if (i >= n4) return;
    float4 v = reinterpret_cast<const float4*>(in)[i];
    __nv_bfloat16 h0 = __float2bfloat16(v.x);
    __nv_bfloat16 h1 = __float2bfloat16(v.y);
    __nv_bfloat16 h2 = __float2bfloat16(v.z);
    __nv_bfloat16 h3 = __float2bfloat16(v.w);
    __nv_bfloat16 l0 = __float2bfloat16(v.x - __bfloat162float(h0));
    __nv_bfloat16 l1 = __float2bfloat16(v.y - __bfloat162float(h1));
    __nv_bfloat16 l2 = __float2bfloat16(v.z - __bfloat162float(h2));
    __nv_bfloat16 l3 = __float2bfloat16(v.w - __bfloat162float(h3));
    hi[i * 4 + 0] = h0; hi[i * 4 + 1] = h1; hi[i * 4 + 2] = h2; hi[i * 4 + 3] = h3;
    lo[i * 4 + 0] = l0; lo[i * 4 + 1] = l1; lo[i * 4 + 2] = l2; lo[i * 4 + 3] = l3;
}

// ---------------------------------------------------------------------------
// Tensor-core GEMM on pre-split bf16 operands.
// C[M,N] = (Ah+Al)[M,K] @ (Bh+Bl)[K,N]; fp32 accum; 3-term compensation.
// CTA tile 128x64, BK=16, 8 warps, warp tile 32x32, cp.async double buffer.
// ---------------------------------------------------------------------------
#define A_PAD 24   // 16 data + 8 pad -> 48B row stride (16B-aligned, ldsm conflict-free)
#define B_PAD 72   // 64 data + 8 pad -> 144B row stride

__device__ __forceinline__ void ldsm_x4(uint32_t addr, uint32_t& r0, uint32_t& r1,
                                        uint32_t& r2, uint32_t& r3) {
    asm volatile("ldmatrix.sync.aligned.m8n8.x4.shared.b16 {%0,%1,%2,%3}, [%4];"
                 : "=r"(r0), "=r"(r1), "=r"(r2), "=r"(r3) : "r"(addr));
}
__device__ __forceinline__ void ldsm_x4_t(uint32_t addr, uint32_t& r0, uint32_t& r1,
                                          uint32_t& r2, uint32_t& r3) {
    asm volatile("ldmatrix.sync.aligned.m8n8.x4.trans.shared.b16 {%0,%1,%2,%3}, [%4];"
                 : "=r"(r0), "=r"(r1), "=r"(r2), "=r"(r3) : "r"(addr));
}
__device__ __forceinline__ void mma_bf16(float* d, const uint32_t* a, const uint32_t* b) {
    asm volatile("mma.sync.aligned.m16n8k16.row.col.f32.bf16.bf16.f32 "
                 "{%0,%1,%2,%3}, {%4,%5,%6,%7}, {%8,%9}, {%0,%1,%2,%3};"
                 : "+f"(d[0]), "+f"(d[1]), "+f"(d[2]), "+f"(d[3])
                 : "r"(a[0]), "r"(a[1]), "r"(a[2]), "r"(a[3]), "r"(b[0]), "r"(b[1]));
}
__device__ __forceinline__ void cp_async16(void* smem_dst, const void* gsrc, bool pred) {
    uint32_t saddr = (uint32_t)__cvta_generic_to_shared(smem_dst);
    int sz = pred ? 16 : 0;
    asm volatile("cp.async.cg.shared.global [%0], [%1], 16, %2;"
                 :: "r"(saddr), "l"(gsrc), "r"(sz));
}

__global__ __launch_bounds__(256)
void mma_gemm_pre_kernel(const __nv_bfloat16* __restrict__ Ahg,
                         const __nv_bfloat16* __restrict__ Alg,
                         const __nv_bfloat16* __restrict__ Bhg,
                         const __nv_bfloat16* __restrict__ Blg,
                         float* __restrict__ C, int M, int K, int N) {
    __shared__ __nv_bfloat16 Ah[2][128][A_PAD];
    __shared__ __nv_bfloat16 Al[2][128][A_PAD];
    __shared__ __nv_bfloat16 Bh[2][16][B_PAD];
    __shared__ __nv_bfloat16 Bl[2][16][B_PAD];

    const int tid = threadIdx.x;
    const int wid = tid >> 5;
    const int lane = tid & 31;
    const int warp_m = wid & 3;
    const int warp_n = wid >> 2;
    const int rowBase = blockIdx.y * 128;
    const int colBase = blockIdx.x * 64;

    // A staging: 128 rows x 16 cols = 256 chunks of 8 bf16; one per thread (x2 for h/l)
    const int a_r = tid >> 1;
    const int a_k = (tid & 1) << 3;
    const int arow = rowBase + a_r;
    const bool a_ok = (arow < M);
    // B staging: 16 rows x 64 cols = 128 chunks; tid<128 -> Bh, tid>=128 -> Bl
    const int bt = tid & 127;
    const int b_r = bt >> 3;
    const int b_c = (bt & 7) << 3;
    const bool is_bh = (tid < 128);

    // ldmatrix lane address components
    const int lrow = lane & 7;
    const int lmat = lane >> 3;
    const int a_mloc = ((lmat & 1) << 3) + lrow;
    const int a_khalf = lmat >> 1;
    const int b_krow = ((lmat & 1) << 3) + lrow;
    const int b_nhalf = lmat >> 1;

    float acc[2][4][4];
#pragma unroll
    for (int i = 0; i < 2; i++)
#pragma unroll
        for (int j = 0; j < 4; j++)
#pragma unroll
            for (int q = 0; q < 4; q++) acc[i][j][q] = 0.0f;

    const int KT = K >> 4;

    // issue stage 0
    {
        cp_async16(&Ah[0][a_r][a_k], Ahg + (size_t)arow * K + a_k, a_ok);
        cp_async16(&Al[0][a_r][a_k], Alg + (size_t)arow * K + a_k, a_ok);
        if (is_bh)
            cp_async16(&Bh[0][b_r][b_c], Bhg + (size_t)b_r * N + colBase + b_c, true);
        else
            cp_async16(&Bl[0][b_r][b_c], Blg + (size_t)b_r * N + colBase + b_c, true);
        asm volatile("cp.async.commit_group;");
    }

    int buf = 0;
    for (int kt = 0; kt < KT; kt++) {
        asm volatile("cp.async.wait_group 0;");
        __syncthreads();

        if (kt + 1 < KT) {
            const int k0 = (kt + 1) << 4;
            const int nb = buf ^ 1;
            cp_async16(&Ah[nb][a_r][a_k], Ahg + (size_t)arow * K + k0 + a_k, a_ok);
            cp_async16(&Al[nb][a_r][a_k], Alg + (size_t)arow * K + k0 + a_k, a_ok);
            if (is_bh)
                cp_async16(&Bh[nb][b_r][b_c], Bhg + (size_t)(k0 + b_r) * N + colBase + b_c, true);
            else
                cp_async16(&Bl[nb][b_r][b_c], Blg + (size_t)(k0 + b_r) * N + colBase + b_c, true);
            asm volatile("cp.async.commit_group;");
        }

        uint32_t ah[2][4], al[2][4];
#pragma unroll
        for (int mf = 0; mf < 2; mf++) {
            const int m_base = warp_m * 32 + mf * 16;
            uint32_t addr_h = (uint32_t)__cvta_generic_to_shared(
                &Ah[buf][m_base + a_mloc][a_khalf * 8]);
            ldsm_x4(addr_h, ah[mf][0], ah[mf][1], ah[mf][2], ah[mf][3]);
            uint32_t addr_l = (uint32_t)__cvta_generic_to_shared(
                &Al[buf][m_base + a_mloc][a_khalf * 8]);
            ldsm_x4(addr_l, al[mf][0], al[mf][1], al[mf][2], al[mf][3]);
        }
        uint32_t bh[2][4], bl[2][4];
#pragma unroll
        for (int g = 0; g < 2; g++) {
            const int n_base = warp_n * 32 + g * 16;
            uint32_t addr_h = (uint32_t)__cvta_generic_to_shared(
                &Bh[buf][b_krow][n_base + b_nhalf * 8]);
            ldsm_x4_t(addr_h, bh[g][0], bh[g][1], bh[g][2], bh[g][3]);
            uint32_t addr_l = (uint32_t)__cvta_generic_to_shared(
                &Bl[buf][b_krow][n_base + b_nhalf * 8]);
            ldsm_x4_t(addr_l, bl[g][0], bl[g][1], bl[g][2], bl[g][3]);
        }
#pragma unroll
        for (int mf = 0; mf < 2; mf++) {
#pragma unroll
            for (int g = 0; g < 2; g++) {
#pragma unroll
                for (int h = 0; h < 2; h++) {
                    float* d = acc[mf][g * 2 + h];
                    const uint32_t bhp[2] = {bh[g][h * 2], bh[g][h * 2 + 1]};
                    const uint32_t blp[2] = {bl[g][h * 2], bl[g][h * 2 + 1]};
                    mma_bf16(d, ah[mf], bhp);
                    mma_bf16(d, ah[mf], blp);
                    mma_bf16(d, al[mf], bhp);
                }
            }
        }
        buf ^= 1;
    }

    const int lq = lane >> 2;
    const int lr = lane & 3;
#pragma unroll
    for (int mf = 0; mf < 2; mf++) {
#pragma unroll
        for (int g = 0; g < 2; g++) {
#pragma unroll
            for (int h = 0; h < 2; h++) {
                const float* d = acc[mf][g * 2 + h];
                const int col = colBase + warp_n * 32 + g * 16 + h * 8 + lr * 2;
                const int r0 = rowBase + warp_m * 32 + mf * 16 + lq;
                if (r0 < M)
                    *reinterpret_cast<float2*>(C + (size_t)r0 * N + col) =
                        make_float2(d[0], d[1]);
                const int r1 = r0 + 8;
                if (r1 < M)
                    *reinterpret_cast<float2*>(C + (size_t)r1 * N + col) =
                        make_float2(d[2], d[3]);
            }
        }
    }
}

// ---------------------------------------------------------------------------
// CSR aggregation. MODE 0: write fp32. MODE 1: relu + bf16 split write.
// out[n,:] = bias + h[n,:]*dinv^2 + sum coef*h[src,:]
// ---------------------------------------------------------------------------
template <int MODE>
__global__ __launch_bounds__(256)
void agg_csr_kernel(const float* __restrict__ h, const float* __restrict__ bias,
                    const float* __restrict__ dinv,
                    const int* __restrict__ rowptr, const int* __restrict__ esrc,
                    const float* __restrict__ ecoef,
                    float* __restrict__ outf,
                    __nv_bfloat16* __restrict__ outh,
                    __nv_bfloat16* __restrict__ outl, int n) {
    const int node = blockIdx.x * 4 + (threadIdx.x >> 6);
    if (node >= n) return;
    const int c = (threadIdx.x & 63) << 2;

    const float di = dinv[node];
    const float wself = di * di;
    float4 hv = *reinterpret_cast<const float4*>(h + (size_t)node * DHID + c);
    float4 bb = *reinterpret_cast<const float4*>(bias + c);
    float4 acc;
    acc.x = fmaf(hv.x, wself, bb.x);
    acc.y = fmaf(hv.y, wself, bb.y);
    acc.z = fmaf(hv.z, wself, bb.z);
    acc.w = fmaf(hv.w, wself, bb.w);

    const int beg = rowptr[node];
    const int end = rowptr[node + 1];
    int e = beg;
    for (; e + 2 <= end; e += 2) {
        const int s0 = esrc[e];
        const int s1 = esrc[e + 1];
        const float c0 = ecoef[e];
        const float c1 = ecoef[e + 1];
        float4 v0 = *reinterpret_cast<const float4*>(h + (size_t)s0 * DHID + c);
        float4 v1 = *reinterpret_cast<const float4*>(h + (size_t)s1 * DHID + c);
        acc.x += c0 * v0.x + c1 * v1.x;
        acc.y += c0 * v0.y + c1 * v1.y;
        acc.z += c0 * v0.z + c1 * v1.z;
        acc.w += c0 * v0.w + c1 * v1.w;
    }
    if (e < end) {
        const int s0 = esrc[e];
        const float c0 = ecoef[e];
        float4 v0 = *reinterpret_cast<const float4*>(h + (size_t)s0 * DHID + c);
        acc.x += c0 * v0.x;
        acc.y += c0 * v0.y;
        acc.z += c0 * v0.z;
        acc.w += c0 * v0.w;
    }

    if (MODE == 0) {
        *reinterpret_cast<float4*>(outf + (size_t)node * DHID + c) = acc;
    } else {
        // relu + split
        float v0 = fmaxf(acc.x, 0.f), v1 = fmaxf(acc.y, 0.f);
        float v2 = fmaxf(acc.z, 0.f), v3 = fmaxf(acc.w, 0.f);
        __nv_bfloat16 h0 = __float2bfloat16(v0);
        __nv_bfloat16 h1 = __float2bfloat16(v1);
        __nv_bfloat16 h2 = __float2bfloat16(v2);
        __nv_bfloat16 h3 = __float2bfloat16(v3);
        __nv_bfloat16 l0 = __float2bfloat16(v0 - __bfloat162float(h0));
        __nv_bfloat16 l1 = __float2bfloat16(v1 - __bfloat162float(h1));
        __nv_bfloat16 l2 = __float2bfloat16(v2 - __bfloat162float(h2));
        __nv_bfloat16 l3 = __float2bfloat16(v3 - __bfloat162float(h3));
        __nv_bfloat16* ph = outh + (size_t)node * DHID + c;
        __nv_bfloat16* pl = outl + (size_t)node * DHID + c;
        ph[0] = h0; ph[1] = h1; ph[2] = h2; ph[3] = h3;
        pl[0] = l0; pl[1] = l1; pl[2] = l2; pl[3] = l3;
    }
}

// ---------------------------------------------------------------------------
// CSR edge scoring: per dst node, load h[dst] once, stream neighbors.
// out[eid[e]] = sigmoid(dot(h[esrc[e]], h[dst]))
// ---------------------------------------------------------------------------
__global__ __launch_bounds__(256)
void score_csr_kernel(const float* __restrict__ h,
                      const int* __restrict__ rowptr,
                      const int* __restrict__ esrc,
                      const int* __restrict__ eid,
                      float* __restrict__ out, int n) {
    const int node = (blockIdx.x * 256 + threadIdx.x) >> 5;
    const int lane = threadIdx.x & 31;
    if (node >= n) return;
    const int beg = rowptr[node];
    const int end = rowptr[node + 1];
    if (beg == end) return;

    const float4* pd = reinterpret_cast<const float4*>(h + (size_t)node * DHID) + lane * 2;
    const float4 d0 = pd[0], d1 = pd[1];

    for (int e = beg; e < end; e++) {
        const int s = esrc[e];
        const float4* ps = reinterpret_cast<const float4*>(h + (size_t)s * DHID) + lane * 2;
        float4 a0 = ps[0], a1 = ps[1];
        float acc = a0.x * d0.x + a0.y * d0.y + a0.z * d0.z + a0.w * d0.w;
        acc += a1.x * d1.x + a1.y * d1.y + a1.z * d1.z + a1.w * d1.w;
#pragma unroll
        for (int off = 16; off > 0; off >>= 1)
            acc += __shfl_xor_sync(0xFFFFFFFFu, acc, off);
        if (lane == 0) out[eid[e]] = 1.0f / (1.0f + expf(-acc));
    }
}

// ---------------------------------------------------------------------------
// Host launcher
// ---------------------------------------------------------------------------
extern "C" void kernel_launch(void* const* d_in, const int* in_sizes, int n_in,
                              void* d_out, int out_size) {
    const float* x  = (const float*)d_in[0];
    const int*   ei = (const int*)d_in[1];
    const float* W1 = (const float*)d_in[2];
    const float* b1 = (const float*)d_in[3];
    const float* W2 = (const float*)d_in[4];
    const float* b2 = (const float*)d_in[5];
    float* out = (float*)d_out;

    const int N = in_sizes[0] / DIN;
    const int E = in_sizes[1] / 2;
    const int* src = ei;
    const int* dst = ei + E;

    int *p_cnt, *p_rowptr, *p_off, *p_esrc, *p_eid, *p_bsum, *p_boff;
    float *p_dinv, *p_ecoef, *p_h1, *p_h2, *p_agg2;
    __nv_bfloat16 *p_xh, *p_xl, *p_w1h, *p_w1l, *p_w2h, *p_w2l, *p_a1h, *p_a1l;
    cudaGetSymbolAddress((void**)&p_cnt,    g_cnt);
    cudaGetSymbolAddress((void**)&p_dinv,   g_dinv);
    cudaGetSymbolAddress((void**)&p_rowptr, g_rowptr);
    cudaGetSymbolAddress((void**)&p_off,    g_off);
    cudaGetSymbolAddress((void**)&p_bsum,   g_blocksum);
    cudaGetSymbolAddress((void**)&p_boff,   g_blockoff);
    cudaGetSymbolAddress((void**)&p_esrc,   g_esrc);
    cudaGetSymbolAddress((void**)&p_eid,    g_eid);
    cudaGetSymbolAddress((void**)&p_ecoef,  g_ecoef);
    cudaGetSymbolAddress((void**)&p_xh,     g_xh);
    cudaGetSymbolAddress((void**)&p_xl,     g_xl);
    cudaGetSymbolAddress((void**)&p_w1h,    g_w1h);
    cudaGetSymbolAddress((void**)&p_w1l,    g_w1l);
    cudaGetSymbolAddress((void**)&p_w2h,    g_w2h);
    cudaGetSymbolAddress((void**)&p_w2l,    g_w2l);
    cudaGetSymbolAddress((void**)&p_h1,     g_h1);
    cudaGetSymbolAddress((void**)&p_a1h,    g_a1h);
    cudaGetSymbolAddress((void**)&p_a1l,    g_a1l);
    cudaGetSymbolAddress((void**)&p_h2,     g_h2);
    cudaGetSymbolAddress((void**)&p_agg2,   g_agg2);

    const int T = 256;

    // 1) CSR build + normalization
    zero_cnt_kernel<<<(N + T - 1) / T, T>>>(p_cnt, N);
    hist_kernel<<<(E + T - 1) / T, T>>>(p_cnt, dst, E);
    dinv_kernel<<<(N + T - 1) / T, T>>>(p_cnt, p_dinv, N);
    scan_p1_kernel<<<NB_SCAN, 256>>>(p_cnt, p_bsum, N);
    scan_p2_kernel<<<1, NB_SCAN>>>(p_bsum, p_boff, p_rowptr, N);
    scan_p3_kernel<<<NB_SCAN, 256>>>(p_cnt, p_boff, p_rowptr, p_off, N);
    scatter_kernel<<<(E + T - 1) / T, T>>>(src, dst, p_dinv, p_off, p_esrc, p_eid, p_ecoef, E);

    // 2) pre-split operands to bf16 (hi, lo)
    {
        int n4 = N * DIN / 4;
        split_kernel<<<(n4 + T - 1) / T, T>>>(x, p_xh, p_xl, n4);
        int w1n4 = DIN * DHID / 4;
        split_kernel<<<(w1n4 + T - 1) / T, T>>>(W1, p_w1h, p_w1l, w1n4);
        int w2n4 = DHID * DHID / 4;
        split_kernel<<<(w2n4 + T - 1) / T, T>>>(W2, p_w2h, p_w2l, w2n4);
    }

    // 3) layer 1: h1 = x @ W1 ; agg1 -> relu + split (feeds GEMM2 directly)
    {
        dim3 grid(DHID / 64, (N + 127) / 128);
        mma_gemm_pre_kernel<<<grid, 256>>>(p_xh, p_xl, p_w1h, p_w1l, p_h1, N, DIN, DHID);
    }
    agg_csr_kernel<1><<<(N + 3) / 4, 256>>>(p_h1, b1, p_dinv, p_rowptr, p_esrc, p_ecoef,
                                            nullptr, p_a1h, p_a1l, N);

    // 4) layer 2: h2 = relu(agg1) @ W2 ; agg2 fp32
    {
        dim3 grid(DHID / 64, (N + 127) / 128);
        mma_gemm_pre_kernel<<<grid, 256>>>(p_a1h, p_a1l, p_w2h, p_w2l, p_h2, N, DHID, DHID);
    }
    agg_csr_kernel<0><<<(N + 3) / 4, 256>>>(p_h2, b2, p_dinv, p_rowptr, p_esrc, p_ecoef,
                                            p_agg2, nullptr, nullptr, N);

    // 5) edge scoring via CSR (h[dst] loaded once per node)
    score_csr_kernel<<<((unsigned)N * 32 + T - 1) / T, T>>>(p_agg2, p_rowptr, p_esrc, p_eid, out, N);
}

// round 6
// speedup vs baseline: 1.3825x; 1.3825x over previous
#include <cuda_runtime.h>
#include <cuda_bf16.h>
#include <stdint.h>
#include <math.h>

#define MAX_N 50000
#define MAX_E 800000
#define DHID 256
#define DIN 512
#define NB_SCAN 128

// Scratch device globals
__device__ int   g_cnt[MAX_N];
__device__ float g_dinv[MAX_N];
__device__ int   g_rowptr[MAX_N + 1];
__device__ int   g_off[MAX_N];
__device__ int   g_blocksum[NB_SCAN];
__device__ int   g_blockoff[NB_SCAN];
__device__ int   g_esrc[MAX_E];
__device__ float g_ecoef[MAX_E];

__device__ __nv_bfloat16 g_xh[(size_t)MAX_N * DIN];
__device__ __nv_bfloat16 g_xl[(size_t)MAX_N * DIN];
__device__ __nv_bfloat16 g_w1h[DIN * DHID];
__device__ __nv_bfloat16 g_w1l[DIN * DHID];
__device__ __nv_bfloat16 g_w2h[DHID * DHID];
__device__ __nv_bfloat16 g_w2l[DHID * DHID];
__device__ float g_h1[(size_t)MAX_N * DHID];
__device__ __nv_bfloat16 g_a1h[(size_t)MAX_N * DHID];
__device__ __nv_bfloat16 g_a1l[(size_t)MAX_N * DHID];
__device__ float g_h2[(size_t)MAX_N * DHID];
__device__ float g_agg2[(size_t)MAX_N * DHID];

// ---------------------------------------------------------------------------
// CSR build
// ---------------------------------------------------------------------------
__global__ void zero_cnt_kernel(int* cnt, int n) {
    int i = blockIdx.x * blockDim.x + threadIdx.x;
    if (i < n) cnt[i] = 0;
}

__global__ void hist_kernel(int* cnt, const int* __restrict__ dst, int e) {
    int i = blockIdx.x * blockDim.x + threadIdx.x;
    if (i < e) atomicAdd(&cnt[dst[i]], 1);
}

__global__ void dinv_kernel(const int* __restrict__ cnt, float* __restrict__ dinv, int n) {
    int i = blockIdx.x * blockDim.x + threadIdx.x;
    if (i < n) dinv[i] = rsqrtf((float)(cnt[i] + 1));
}

__global__ __launch_bounds__(256)
void scan_p1_kernel(const int* __restrict__ cnt, int* __restrict__ blocksum, int n) {
    __shared__ int red[256];
    const int chunk = (n + NB_SCAN - 1) / NB_SCAN;
    const int beg = blockIdx.x * chunk;
    const int end = min(beg + chunk, n);
    int s = 0;
    for (int i = beg + threadIdx.x; i < end; i += 256) s += cnt[i];
    red[threadIdx.x] = s;
    __syncthreads();
    for (int d = 128; d > 0; d >>= 1) {
        if (threadIdx.x < d) red[threadIdx.x] += red[threadIdx.x + d];
        __syncthreads();
    }
    if (threadIdx.x == 0) blocksum[blockIdx.x] = red[0];
}

__global__ __launch_bounds__(NB_SCAN)
void scan_p2_kernel(const int* __restrict__ blocksum, int* __restrict__ blockoff,
                    int* __restrict__ rowptr, int n) {
    __shared__ int sh[NB_SCAN];
    const int t = threadIdx.x;
    sh[t] = blocksum[t];
    __syncthreads();
    for (int d = 1; d < NB_SCAN; d <<= 1) {
        int v = (t >= d) ? sh[t - d] : 0;
        __syncthreads();
        sh[t] += v;
        __syncthreads();
    }
    blockoff[t] = (t == 0) ? 0 : sh[t - 1];
    if (t == NB_SCAN - 1) rowptr[n] = sh[NB_SCAN - 1];
}

__global__ __launch_bounds__(256)
void scan_p3_kernel(const int* __restrict__ cnt, const int* __restrict__ blockoff,
                    int* __restrict__ rowptr, int* __restrict__ off, int n) {
    __shared__ int sh[256];
    const int chunk = (n + NB_SCAN - 1) / NB_SCAN;
    const int beg = blockIdx.x * chunk;
    const int end = min(beg + chunk, n);
    int running = blockoff[blockIdx.x];
    for (int base = beg; base < end; base += 256) {
        const int i = base + threadIdx.x;
        int v = (i < end) ? cnt[i] : 0;
        sh[threadIdx.x] = v;
        __syncthreads();
        for (int d = 1; d < 256; d <<= 1) {
            int t2 = (threadIdx.x >= d) ? sh[threadIdx.x - d] : 0;
            __syncthreads();
            sh[threadIdx.x] += t2;
            __syncthreads();
        }
        if (i < end) {
            const int excl = sh[threadIdx.x] - v;
            rowptr[i] = running + excl;
            off[i] = running + excl;
        }
        running += sh[255];
        __syncthreads();
    }
}

__global__ void scatter_kernel(const int* __restrict__ src, const int* __restrict__ dst,
                               const float* __restrict__ dinv, int* __restrict__ off,
                               int* __restrict__ esrc, float* __restrict__ ecoef, int e) {
    int i = blockIdx.x * blockDim.x + threadIdx.x;
    if (i < e) {
        const int s = src[i];
        const int d = dst[i];
        const int pos = atomicAdd(&off[d], 1);
        esrc[pos] = s;
        ecoef[pos] = dinv[s] * dinv[d];
    }
}

// ---------------------------------------------------------------------------
// fp32 -> (hi, lo) bf16 split, elementwise (for x, W1, W2)
// ---------------------------------------------------------------------------
__global__ void split_kernel(const float* __restrict__ in,
                             __nv_bfloat16* __restrict__ hi,
                             __nv_bfloat16* __restrict__ lo, int n4) {
    int i = blockIdx.x * blockDim.x + threadIdx.x;
    if (i >= n4) return;
    float4 v = reinterpret_cast<const float4*>(in)[i];
    __nv_bfloat16 h0 = __float2bfloat16(v.x);
    __nv_bfloat16 h1 = __float2bfloat16(v.y);
    __nv_bfloat16 h2 = __float2bfloat16(v.z);
    __nv_bfloat16 h3 = __float2bfloat16(v.w);
    __nv_bfloat16 l0 = __float2bfloat16(v.x - __bfloat162float(h0));
    __nv_bfloat16 l1 = __float2bfloat16(v.y - __bfloat162float(h1));
    __nv_bfloat16 l2 = __float2bfloat16(v.z - __bfloat162float(h2));
    __nv_bfloat16 l3 = __float2bfloat16(v.w - __bfloat162float(h3));
    hi[i * 4 + 0] = h0; hi[i * 4 + 1] = h1; hi[i * 4 + 2] = h2; hi[i * 4 + 3] = h3;
    lo[i * 4 + 0] = l0; lo[i * 4 + 1] = l1; lo[i * 4 + 2] = l2; lo[i * 4 + 3] = l3;
}

// ---------------------------------------------------------------------------
// Tensor-core GEMM on pre-split bf16 operands.
// C[M,N] = (Ah+Al)[M,K] @ (Bh+Bl)[K,N]; fp32 accum; 3-term compensation.
// CTA tile 128x64, BK=16, 8 warps, warp tile 32x32, cp.async double buffer.
// ---------------------------------------------------------------------------
#define A_PAD 24
#define B_PAD 72

__device__ __forceinline__ void ldsm_x4(uint32_t addr, uint32_t& r0, uint32_t& r1,
                                        uint32_t& r2, uint32_t& r3) {
    asm volatile("ldmatrix.sync.aligned.m8n8.x4.shared.b16 {%0,%1,%2,%3}, [%4];"
                 : "=r"(r0), "=r"(r1), "=r"(r2), "=r"(r3) : "r"(addr));
}
__device__ __forceinline__ void ldsm_x4_t(uint32_t addr, uint32_t& r0, uint32_t& r1,
                                          uint32_t& r2, uint32_t& r3) {
    asm volatile("ldmatrix.sync.aligned.m8n8.x4.trans.shared.b16 {%0,%1,%2,%3}, [%4];"
                 : "=r"(r0), "=r"(r1), "=r"(r2), "=r"(r3) : "r"(addr));
}
__device__ __forceinline__ void mma_bf16(float* d, const uint32_t* a, const uint32_t* b) {
    asm volatile("mma.sync.aligned.m16n8k16.row.col.f32.bf16.bf16.f32 "
                 "{%0,%1,%2,%3}, {%4,%5,%6,%7}, {%8,%9}, {%0,%1,%2,%3};"
                 : "+f"(d[0]), "+f"(d[1]), "+f"(d[2]), "+f"(d[3])
                 : "r"(a[0]), "r"(a[1]), "r"(a[2]), "r"(a[3]), "r"(b[0]), "r"(b[1]));
}
__device__ __forceinline__ void cp_async16(void* smem_dst, const void* gsrc, bool pred) {
    uint32_t saddr = (uint32_t)__cvta_generic_to_shared(smem_dst);
    int sz = pred ? 16 : 0;
    asm volatile("cp.async.cg.shared.global [%0], [%1], 16, %2;"
                 :: "r"(saddr), "l"(gsrc), "r"(sz));
}

__global__ __launch_bounds__(256)
void mma_gemm_pre_kernel(const __nv_bfloat16* __restrict__ Ahg,
                         const __nv_bfloat16* __restrict__ Alg,
                         const __nv_bfloat16* __restrict__ Bhg,
                         const __nv_bfloat16* __restrict__ Blg,
                         float* __restrict__ C, int M, int K, int N) {
    __shared__ __nv_bfloat16 Ah[2][128][A_PAD];
    __shared__ __nv_bfloat16 Al[2][128][A_PAD];
    __shared__ __nv_bfloat16 Bh[2][16][B_PAD];
    __shared__ __nv_bfloat16 Bl[2][16][B_PAD];

    const int tid = threadIdx.x;
    const int wid = tid >> 5;
    const int lane = tid & 31;
    const int warp_m = wid & 3;
    const int warp_n = wid >> 2;
    const int rowBase = blockIdx.y * 128;
    const int colBase = blockIdx.x * 64;

    const int a_r = tid >> 1;
    const int a_k = (tid & 1) << 3;
    const int arow = rowBase + a_r;
    const bool a_ok = (arow < M);
    const int bt = tid & 127;
    const int b_r = bt >> 3;
    const int b_c = (bt & 7) << 3;
    const bool is_bh = (tid < 128);

    const int lrow = lane & 7;
    const int lmat = lane >> 3;
    const int a_mloc = ((lmat & 1) << 3) + lrow;
    const int a_khalf = lmat >> 1;
    const int b_krow = ((lmat & 1) << 3) + lrow;
    const int b_nhalf = lmat >> 1;

    float acc[2][4][4];
#pragma unroll
    for (int i = 0; i < 2; i++)
#pragma unroll
        for (int j = 0; j < 4; j++)
#pragma unroll
            for (int q = 0; q < 4; q++) acc[i][j][q] = 0.0f;

    const int KT = K >> 4;

    {
        cp_async16(&Ah[0][a_r][a_k], Ahg + (size_t)arow * K + a_k, a_ok);
        cp_async16(&Al[0][a_r][a_k], Alg + (size_t)arow * K + a_k, a_ok);
        if (is_bh)
            cp_async16(&Bh[0][b_r][b_c], Bhg + (size_t)b_r * N + colBase + b_c, true);
        else
            cp_async16(&Bl[0][b_r][b_c], Blg + (size_t)b_r * N + colBase + b_c, true);
        asm volatile("cp.async.commit_group;");
    }

    int buf = 0;
    for (int kt = 0; kt < KT; kt++) {
        asm volatile("cp.async.wait_group 0;");
        __syncthreads();

        if (kt + 1 < KT) {
            const int k0 = (kt + 1) << 4;
            const int nb = buf ^ 1;
            cp_async16(&Ah[nb][a_r][a_k], Ahg + (size_t)arow * K + k0 + a_k, a_ok);
            cp_async16(&Al[nb][a_r][a_k], Alg + (size_t)arow * K + k0 + a_k, a_ok);
            if (is_bh)
                cp_async16(&Bh[nb][b_r][b_c], Bhg + (size_t)(k0 + b_r) * N + colBase + b_c, true);
            else
                cp_async16(&Bl[nb][b_r][b_c], Blg + (size_t)(k0 + b_r) * N + colBase + b_c, true);
            asm volatile("cp.async.commit_group;");
        }

        uint32_t ah[2][4], al[2][4];
#pragma unroll
        for (int mf = 0; mf < 2; mf++) {
            const int m_base = warp_m * 32 + mf * 16;
            uint32_t addr_h = (uint32_t)__cvta_generic_to_shared(
                &Ah[buf][m_base + a_mloc][a_khalf * 8]);
            ldsm_x4(addr_h, ah[mf][0], ah[mf][1], ah[mf][2], ah[mf][3]);
            uint32_t addr_l = (uint32_t)__cvta_generic_to_shared(
                &Al[buf][m_base + a_mloc][a_khalf * 8]);
            ldsm_x4(addr_l, al[mf][0], al[mf][1], al[mf][2], al[mf][3]);
        }
        uint32_t bh[2][4], bl[2][4];
#pragma unroll
        for (int g = 0; g < 2; g++) {
            const int n_base = warp_n * 32 + g * 16;
            uint32_t addr_h = (uint32_t)__cvta_generic_to_shared(
                &Bh[buf][b_krow][n_base + b_nhalf * 8]);
            ldsm_x4_t(addr_h, bh[g][0], bh[g][1], bh[g][2], bh[g][3]);
            uint32_t addr_l = (uint32_t)__cvta_generic_to_shared(
                &Bl[buf][b_krow][n_base + b_nhalf * 8]);
            ldsm_x4_t(addr_l, bl[g][0], bl[g][1], bl[g][2], bl[g][3]);
        }
#pragma unroll
        for (int mf = 0; mf < 2; mf++) {
#pragma unroll
            for (int g = 0; g < 2; g++) {
#pragma unroll
                for (int h = 0; h < 2; h++) {
                    float* d = acc[mf][g * 2 + h];
                    const uint32_t bhp[2] = {bh[g][h * 2], bh[g][h * 2 + 1]};
                    const uint32_t blp[2] = {bl[g][h * 2], bl[g][h * 2 + 1]};
                    mma_bf16(d, ah[mf], bhp);
                    mma_bf16(d, ah[mf], blp);
                    mma_bf16(d, al[mf], bhp);
                }
            }
        }
        buf ^= 1;
    }

    const int lq = lane >> 2;
    const int lr = lane & 3;
#pragma unroll
    for (int mf = 0; mf < 2; mf++) {
#pragma unroll
        for (int g = 0; g < 2; g++) {
#pragma unroll
            for (int h = 0; h < 2; h++) {
                const float* d = acc[mf][g * 2 + h];
                const int col = colBase + warp_n * 32 + g * 16 + h * 8 + lr * 2;
                const int r0 = rowBase + warp_m * 32 + mf * 16 + lq;
                if (r0 < M)
                    *reinterpret_cast<float2*>(C + (size_t)r0 * N + col) =
                        make_float2(d[0], d[1]);
                const int r1 = r0 + 8;
                if (r1 < M)
                    *reinterpret_cast<float2*>(C + (size_t)r1 * N + col) =
                        make_float2(d[2], d[3]);
            }
        }
    }
}

// ---------------------------------------------------------------------------
// CSR aggregation. MODE 0: write fp32. MODE 1: relu + bf16 split write.
// ---------------------------------------------------------------------------
template <int MODE>
__global__ __launch_bounds__(256)
void agg_csr_kernel(const float* __restrict__ h, const float* __restrict__ bias,
                    const float* __restrict__ dinv,
                    const int* __restrict__ rowptr, const int* __restrict__ esrc,
                    const float* __restrict__ ecoef,
                    float* __restrict__ outf,
                    __nv_bfloat16* __restrict__ outh,
                    __nv_bfloat16* __restrict__ outl, int n) {
    const int node = blockIdx.x * 4 + (threadIdx.x >> 6);
    if (node >= n) return;
    const int c = (threadIdx.x & 63) << 2;

    const float di = dinv[node];
    const float wself = di * di;
    float4 hv = *reinterpret_cast<const float4*>(h + (size_t)node * DHID + c);
    float4 bb = *reinterpret_cast<const float4*>(bias + c);
    float4 acc;
    acc.x = fmaf(hv.x, wself, bb.x);
    acc.y = fmaf(hv.y, wself, bb.y);
    acc.z = fmaf(hv.z, wself, bb.z);
    acc.w = fmaf(hv.w, wself, bb.w);

    const int beg = rowptr[node];
    const int end = rowptr[node + 1];
    int e = beg;
    for (; e + 2 <= end; e += 2) {
        const int s0 = esrc[e];
        const int s1 = esrc[e + 1];
        const float c0 = ecoef[e];
        const float c1 = ecoef[e + 1];
        float4 v0 = *reinterpret_cast<const float4*>(h + (size_t)s0 * DHID + c);
        float4 v1 = *reinterpret_cast<const float4*>(h + (size_t)s1 * DHID + c);
        acc.x += c0 * v0.x + c1 * v1.x;
        acc.y += c0 * v0.y + c1 * v1.y;
        acc.z += c0 * v0.z + c1 * v1.z;
        acc.w += c0 * v0.w + c1 * v1.w;
    }
    if (e < end) {
        const int s0 = esrc[e];
        const float c0 = ecoef[e];
        float4 v0 = *reinterpret_cast<const float4*>(h + (size_t)s0 * DHID + c);
        acc.x += c0 * v0.x;
        acc.y += c0 * v0.y;
        acc.z += c0 * v0.z;
        acc.w += c0 * v0.w;
    }

    if (MODE == 0) {
        *reinterpret_cast<float4*>(outf + (size_t)node * DHID + c) = acc;
    } else {
        float v0 = fmaxf(acc.x, 0.f), v1 = fmaxf(acc.y, 0.f);
        float v2 = fmaxf(acc.z, 0.f), v3 = fmaxf(acc.w, 0.f);
        __nv_bfloat16 h0 = __float2bfloat16(v0);
        __nv_bfloat16 h1 = __float2bfloat16(v1);
        __nv_bfloat16 h2 = __float2bfloat16(v2);
        __nv_bfloat16 h3 = __float2bfloat16(v3);
        __nv_bfloat16 l0 = __float2bfloat16(v0 - __bfloat162float(h0));
        __nv_bfloat16 l1 = __float2bfloat16(v1 - __bfloat162float(h1));
        __nv_bfloat16 l2 = __float2bfloat16(v2 - __bfloat162float(h2));
        __nv_bfloat16 l3 = __float2bfloat16(v3 - __bfloat162float(h3));
        __nv_bfloat16* ph = outh + (size_t)node * DHID + c;
        __nv_bfloat16* pl = outl + (size_t)node * DHID + c;
        ph[0] = h0; ph[1] = h1; ph[2] = h2; ph[3] = h3;
        pl[0] = l0; pl[1] = l1; pl[2] = l2; pl[3] = l3;
    }
}

// ---------------------------------------------------------------------------
// Edge scoring (edge-parallel: one warp per edge)
// ---------------------------------------------------------------------------
__global__ __launch_bounds__(256)
void score_kernel(const float* __restrict__ h,
                  const int* __restrict__ src,
                  const int* __restrict__ dst,
                  float* __restrict__ out, int e) {
    unsigned gt = blockIdx.x * blockDim.x + threadIdx.x;
    unsigned ed = gt >> 5;
    const int lane = threadIdx.x & 31;
    if (ed >= (unsigned)e) return;
    const int s = src[ed];
    const int d = dst[ed];
    const float4* ps = reinterpret_cast<const float4*>(h + (size_t)s * DHID) + lane * 2;
    const float4* pd = reinterpret_cast<const float4*>(h + (size_t)d * DHID) + lane * 2;
    float4 a0 = ps[0], a1 = ps[1];
    float4 b0 = pd[0], b1 = pd[1];
    float acc = a0.x * b0.x + a0.y * b0.y + a0.z * b0.z + a0.w * b0.w;
    acc += a1.x * b1.x + a1.y * b1.y + a1.z * b1.z + a1.w * b1.w;
#pragma unroll
    for (int off = 16; off > 0; off >>= 1)
        acc += __shfl_xor_sync(0xFFFFFFFFu, acc, off);
    if (lane == 0) out[ed] = 1.0f / (1.0f + expf(-acc));
}

// ---------------------------------------------------------------------------
// Host launcher
// ---------------------------------------------------------------------------
extern "C" void kernel_launch(void* const* d_in, const int* in_sizes, int n_in,
                              void* d_out, int out_size) {
    const float* x  = (const float*)d_in[0];
    const int*   ei = (const int*)d_in[1];
    const float* W1 = (const float*)d_in[2];
    const float* b1 = (const float*)d_in[3];
    const float* W2 = (const float*)d_in[4];
    const float* b2 = (const float*)d_in[5];
    float* out = (float*)d_out;

    const int N = in_sizes[0] / DIN;
    const int E = in_sizes[1] / 2;
    const int* src = ei;
    const int* dst = ei + E;

    int *p_cnt, *p_rowptr, *p_off, *p_esrc, *p_bsum, *p_boff;
    float *p_dinv, *p_ecoef, *p_h1, *p_h2, *p_agg2;
    __nv_bfloat16 *p_xh, *p_xl, *p_w1h, *p_w1l, *p_w2h, *p_w2l, *p_a1h, *p_a1l;
    cudaGetSymbolAddress((void**)&p_cnt,    g_cnt);
    cudaGetSymbolAddress((void**)&p_dinv,   g_dinv);
    cudaGetSymbolAddress((void**)&p_rowptr, g_rowptr);
    cudaGetSymbolAddress((void**)&p_off,    g_off);
    cudaGetSymbolAddress((void**)&p_bsum,   g_blocksum);
    cudaGetSymbolAddress((void**)&p_boff,   g_blockoff);
    cudaGetSymbolAddress((void**)&p_esrc,   g_esrc);
    cudaGetSymbolAddress((void**)&p_ecoef,  g_ecoef);
    cudaGetSymbolAddress((void**)&p_xh,     g_xh);
    cudaGetSymbolAddress((void**)&p_xl,     g_xl);
    cudaGetSymbolAddress((void**)&p_w1h,    g_w1h);
    cudaGetSymbolAddress((void**)&p_w1l,    g_w1l);
    cudaGetSymbolAddress((void**)&p_w2h,    g_w2h);
    cudaGetSymbolAddress((void**)&p_w2l,    g_w2l);
    cudaGetSymbolAddress((void**)&p_h1,     g_h1);
    cudaGetSymbolAddress((void**)&p_a1h,    g_a1h);
    cudaGetSymbolAddress((void**)&p_a1l,    g_a1l);
    cudaGetSymbolAddress((void**)&p_h2,     g_h2);
    cudaGetSymbolAddress((void**)&p_agg2,   g_agg2);

    const int T = 256;

    // 1) CSR build + normalization
    zero_cnt_kernel<<<(N + T - 1) / T, T>>>(p_cnt, N);
    hist_kernel<<<(E + T - 1) / T, T>>>(p_cnt, dst, E);
    dinv_kernel<<<(N + T - 1) / T, T>>>(p_cnt, p_dinv, N);
    scan_p1_kernel<<<NB_SCAN, 256>>>(p_cnt, p_bsum, N);
    scan_p2_kernel<<<1, NB_SCAN>>>(p_bsum, p_boff, p_rowptr, N);
    scan_p3_kernel<<<NB_SCAN, 256>>>(p_cnt, p_boff, p_rowptr, p_off, N);
    scatter_kernel<<<(E + T - 1) / T, T>>>(src, dst, p_dinv, p_off, p_esrc, p_ecoef, E);

    // 2) pre-split operands to bf16 (hi, lo)
    {
        int n4 = N * DIN / 4;
        split_kernel<<<(n4 + T - 1) / T, T>>>(x, p_xh, p_xl, n4);
        int w1n4 = DIN * DHID / 4;
        split_kernel<<<(w1n4 + T - 1) / T, T>>>(W1, p_w1h, p_w1l, w1n4);
        int w2n4 = DHID * DHID / 4;
        split_kernel<<<(w2n4 + T - 1) / T, T>>>(W2, p_w2h, p_w2l, w2n4);
    }

    // 3) layer 1: h1 = x @ W1 ; agg1 -> relu + split (feeds GEMM2 directly)
    {
        dim3 grid(DHID / 64, (N + 127) / 128);
        mma_gemm_pre_kernel<<<grid, 256>>>(p_xh, p_xl, p_w1h, p_w1l, p_h1, N, DIN, DHID);
    }
    agg_csr_kernel<1><<<(N + 3) / 4, 256>>>(p_h1, b1, p_dinv, p_rowptr, p_esrc, p_ecoef,
                                            nullptr, p_a1h, p_a1l, N);

    // 4) layer 2: h2 = relu(agg1) @ W2 ; agg2 fp32
    {
        dim3 grid(DHID / 64, (N + 127) / 128);
        mma_gemm_pre_kernel<<<grid, 256>>>(p_a1h, p_a1l, p_w2h, p_w2l, p_h2, N, DHID, DHID);
    }
    agg_csr_kernel<0><<<(N + 3) / 4, 256>>>(p_h2, b2, p_dinv, p_rowptr, p_esrc, p_ecoef,
                                            p_agg2, nullptr, nullptr, N);

    // 5) edge scoring (edge-parallel)
    score_kernel<<<((unsigned)E * 32 + T - 1) / T, T>>>(p_agg2, src, dst, out, E);
}